// round 4
// baseline (speedup 1.0000x reference)
#include <cuda_runtime.h>
#include <cuda_fp16.h>
#include <math.h>

#define N_NODES 20000
#define N_EDGES 5000
#define D       128
#define ATT     32
#define ECAP    384
#define NCAP    128
#define LN_EPS  1e-5f
#define DEG_EPS 1e-12f
#define FULL    0xffffffffu

#define NB      740          // 148 SMs x 5 blocks (co-resident via launch_bounds)
#define NT      256
#define NW      (NB * (NT / 32))   // 5920 warps

// ---------------- device scratch ----------------
__device__ int   g_edge_cnt[N_EDGES];
__device__ int   g_node_cnt[N_NODES];
__device__ int   g_edge_nodes[N_EDGES * ECAP];
__device__ int   g_node_edges[N_NODES * NCAP];
__device__ float g_de_inv[N_EDGES];
__device__ float g_dv_inv[N_NODES];
__device__ uint2  g_x[N_NODES * 32];        // fp16 features (256B rows)
__device__ uint2  g_edge_h[N_EDGES * 32];   // fp16 edge means
__device__ float4 g_edge_out[N_EDGES * 32]; // fp32 final edge_out
__device__ float g_logits[N_EDGES];
__device__ float g_scores[N_EDGES];
__device__ int      g_bar_cnt;              // zero-initialized
__device__ unsigned g_bar_gen;

// ---------------- fp16 helpers ----------------
__device__ __forceinline__ uint2 f4_to_h4(float4 v) {
    __half2 a = __floats2half2_rn(v.x, v.y);
    __half2 b = __floats2half2_rn(v.z, v.w);
    uint2 r; r.x = *(unsigned*)&a; r.y = *(unsigned*)&b; return r;
}
__device__ __forceinline__ float4 h4_to_f4(uint2 v) {
    float2 a = __half22float2(*(__half2*)&v.x);
    float2 b = __half22float2(*(__half2*)&v.y);
    return make_float4(a.x, a.y, b.x, b.y);
}
__device__ __forceinline__ __half2 u2h(unsigned u) { return *(__half2*)&u; }

// ---------------- software grid barrier ----------------
// Producer side: __threadfence() before arrive (drain stores to L2).
// Consumer side: __threadfence() after release (gpu-scope fence ->
// CCTL.IVALL on sm_103a, invalidates stale L1D from the previous phase).
__device__ __forceinline__ void gsync() {
    __syncthreads();
    if (threadIdx.x == 0) {
        volatile unsigned* genp = &g_bar_gen;
        unsigned gen = *genp;
        __threadfence();
        if (atomicAdd(&g_bar_cnt, 1) == NB - 1) {
            g_bar_cnt = 0;
            __threadfence();
            *genp = gen + 1;
        } else {
            while (*genp == gen) __nanosleep(64);
        }
        __threadfence();
    }
    __syncthreads();
}

// ---------------- init: x0 -> fp16 x, zero counters ----------------
__global__ void init_kernel(const float4* __restrict__ x0) {
    int i = blockIdx.x * blockDim.x + threadIdx.x;
    int stride = gridDim.x * blockDim.x;
    for (int k = i; k < N_NODES * 32; k += stride) g_x[k] = f4_to_h4(x0[k]);
    for (int k = i; k < N_EDGES; k += stride) g_edge_cnt[k] = 0;
    for (int k = i; k < N_NODES; k += stride) g_node_cnt[k] = 0;
}

// ---------------- build adjacency (single dense pass over H) ----------------
__global__ void build_kernel(const float* __restrict__ H) {
    const long long total4 = (long long)N_NODES * N_EDGES / 4;
    long long idx = (long long)blockIdx.x * blockDim.x + threadIdx.x;
    long long stride = (long long)gridDim.x * blockDim.x;
    const float4* H4 = (const float4*)H;
    for (long long qq = idx; qq < total4; qq += stride) {
        float4 v = __ldg(&H4[qq]);
        long long l = qq * 4;
        int n = (int)(l / N_EDGES);
        int e = (int)(l % N_EDGES);
        float vals[4] = {v.x, v.y, v.z, v.w};
        #pragma unroll
        for (int c = 0; c < 4; c++) {
            if (vals[c] != 0.0f) {
                int ee = e + c;
                int pe = atomicAdd(&g_edge_cnt[ee], 1);
                if (pe < ECAP) g_edge_nodes[ee * ECAP + pe] = n;
                int pn = atomicAdd(&g_node_cnt[n], 1);
                if (pn < NCAP) g_node_edges[n * NCAP + pn] = ee;
            }
        }
    }
}

// ---------------- phase: V -> E mean (warp per edge) ----------------
template <bool FINAL>
__device__ void v2e_phase(int wid, int lane) {
    for (int e = wid; e < N_EDGES; e += NW) {
        int deg = min(g_edge_cnt[e], ECAP);
        const int* lst = &g_edge_nodes[e * ECAP];
        __half2 z = __floats2half2_rn(0.f, 0.f);
        __half2 a0x = z, a0y = z, a1x = z, a1y = z, a2x = z, a2y = z, a3x = z, a3y = z;
        float4 fs = make_float4(0.f, 0.f, 0.f, 0.f);
        for (int base = 0; base < deg; base += 32) {
            int m = min(32, deg - base);
            int idx = lst[base + min(lane, m - 1)];
            int k = 0;
            for (; k + 4 <= m; k += 4) {
                int n0 = __shfl_sync(FULL, idx, k);
                int n1 = __shfl_sync(FULL, idx, k + 1);
                int n2 = __shfl_sync(FULL, idx, k + 2);
                int n3 = __shfl_sync(FULL, idx, k + 3);
                uint2 v0 = g_x[n0 * 32 + lane];
                uint2 v1 = g_x[n1 * 32 + lane];
                uint2 v2 = g_x[n2 * 32 + lane];
                uint2 v3 = g_x[n3 * 32 + lane];
                if (FINAL) {
                    float4 f0 = h4_to_f4(v0), f1 = h4_to_f4(v1);
                    float4 f2 = h4_to_f4(v2), f3 = h4_to_f4(v3);
                    fs.x += (f0.x + f1.x) + (f2.x + f3.x);
                    fs.y += (f0.y + f1.y) + (f2.y + f3.y);
                    fs.z += (f0.z + f1.z) + (f2.z + f3.z);
                    fs.w += (f0.w + f1.w) + (f2.w + f3.w);
                } else {
                    a0x = __hadd2(a0x, u2h(v0.x)); a0y = __hadd2(a0y, u2h(v0.y));
                    a1x = __hadd2(a1x, u2h(v1.x)); a1y = __hadd2(a1y, u2h(v1.y));
                    a2x = __hadd2(a2x, u2h(v2.x)); a2y = __hadd2(a2y, u2h(v2.y));
                    a3x = __hadd2(a3x, u2h(v3.x)); a3y = __hadd2(a3y, u2h(v3.y));
                }
            }
            for (; k < m; k++) {
                int n0 = __shfl_sync(FULL, idx, k);
                uint2 v0 = g_x[n0 * 32 + lane];
                if (FINAL) {
                    float4 f0 = h4_to_f4(v0);
                    fs.x += f0.x; fs.y += f0.y; fs.z += f0.z; fs.w += f0.w;
                } else {
                    a0x = __hadd2(a0x, u2h(v0.x)); a0y = __hadd2(a0y, u2h(v0.y));
                }
            }
        }
        float s = g_de_inv[e];
        if (FINAL) {
            float4 r;
            r.x = fs.x * s; r.y = fs.y * s; r.z = fs.z * s; r.w = fs.w * s;
            g_edge_out[e * 32 + lane] = r;
        } else {
            float2 sx0 = __half22float2(a0x), sx1 = __half22float2(a1x);
            float2 sx2 = __half22float2(a2x), sx3 = __half22float2(a3x);
            float2 sy0 = __half22float2(a0y), sy1 = __half22float2(a1y);
            float2 sy2 = __half22float2(a2y), sy3 = __half22float2(a3y);
            float4 r;
            r.x = ((sx0.x + sx1.x) + (sx2.x + sx3.x)) * s;
            r.y = ((sx0.y + sx1.y) + (sx2.y + sx3.y)) * s;
            r.z = ((sy0.x + sy1.x) + (sy2.x + sy3.x)) * s;
            r.w = ((sy0.y + sy1.y) + (sy2.y + sy3.y)) * s;
            g_edge_h[e * 32 + lane] = f4_to_h4(r);
        }
    }
}

// ---------------- phase: E -> V mean + residual + LayerNorm (warp per node) ----------------
__device__ void e2v_phase(int wid, int lane,
                          const float4* __restrict__ x0,
                          const float4* __restrict__ gamma,
                          const float4* __restrict__ beta) {
    for (int n = wid; n < N_NODES; n += NW) {
        int deg = min(g_node_cnt[n], NCAP);
        const int* lst = &g_node_edges[n * NCAP];
        __half2 z = __floats2half2_rn(0.f, 0.f);
        __half2 a0x = z, a0y = z, a1x = z, a1y = z, a2x = z, a2y = z, a3x = z, a3y = z;
        for (int base = 0; base < deg; base += 32) {
            int m = min(32, deg - base);
            int idx = lst[base + min(lane, m - 1)];
            int k = 0;
            for (; k + 4 <= m; k += 4) {
                int e0 = __shfl_sync(FULL, idx, k);
                int e1 = __shfl_sync(FULL, idx, k + 1);
                int e2 = __shfl_sync(FULL, idx, k + 2);
                int e3 = __shfl_sync(FULL, idx, k + 3);
                uint2 v0 = g_edge_h[e0 * 32 + lane];
                uint2 v1 = g_edge_h[e1 * 32 + lane];
                uint2 v2 = g_edge_h[e2 * 32 + lane];
                uint2 v3 = g_edge_h[e3 * 32 + lane];
                a0x = __hadd2(a0x, u2h(v0.x)); a0y = __hadd2(a0y, u2h(v0.y));
                a1x = __hadd2(a1x, u2h(v1.x)); a1y = __hadd2(a1y, u2h(v1.y));
                a2x = __hadd2(a2x, u2h(v2.x)); a2y = __hadd2(a2y, u2h(v2.y));
                a3x = __hadd2(a3x, u2h(v3.x)); a3y = __hadd2(a3y, u2h(v3.y));
            }
            for (; k < m; k++) {
                int e0 = __shfl_sync(FULL, idx, k);
                uint2 v0 = g_edge_h[e0 * 32 + lane];
                a0x = __hadd2(a0x, u2h(v0.x)); a0y = __hadd2(a0y, u2h(v0.y));
            }
        }
        float2 sx0 = __half22float2(a0x), sx1 = __half22float2(a1x);
        float2 sx2 = __half22float2(a2x), sx3 = __half22float2(a3x);
        float2 sy0 = __half22float2(a0y), sy1 = __half22float2(a1y);
        float2 sy2 = __half22float2(a2y), sy3 = __half22float2(a3y);
        float s = g_dv_inv[n];
        float4 r = __ldg(&x0[n * 32 + lane]);
        float4 y;
        y.x = ((sx0.x + sx1.x) + (sx2.x + sx3.x)) * s + r.x;
        y.y = ((sx0.y + sx1.y) + (sx2.y + sx3.y)) * s + r.y;
        y.z = ((sy0.x + sy1.x) + (sy2.x + sy3.x)) * s + r.z;
        y.w = ((sy0.y + sy1.y) + (sy2.y + sy3.y)) * s + r.w;

        float sm = (y.x + y.y) + (y.z + y.w);
        #pragma unroll
        for (int o = 16; o > 0; o >>= 1) sm += __shfl_xor_sync(FULL, sm, o);
        float mu = sm * (1.0f / D);
        float4 dy;
        dy.x = y.x - mu; dy.y = y.y - mu; dy.z = y.z - mu; dy.w = y.w - mu;
        float s2 = (dy.x * dy.x + dy.y * dy.y) + (dy.z * dy.z + dy.w * dy.w);
        #pragma unroll
        for (int o = 16; o > 0; o >>= 1) s2 += __shfl_xor_sync(FULL, s2, o);
        float rstd = rsqrtf(s2 * (1.0f / D) + LN_EPS);
        float4 g = __ldg(&gamma[lane]);
        float4 bb = __ldg(&beta[lane]);
        float4 o4;
        o4.x = dy.x * rstd * g.x + bb.x;
        o4.y = dy.y * rstd * g.y + bb.y;
        o4.z = dy.z * rstd * g.z + bb.z;
        o4.w = dy.w * rstd * g.w + bb.w;
        g_x[n * 32 + lane] = f4_to_h4(o4);
    }
}

// ---------------- phase: attention logits (warp per edge) ----------------
__device__ void logits_phase(int wid, int lane,
                             const float* __restrict__ W,
                             const float* __restrict__ b,
                             const float* __restrict__ q) {
    float bj = __ldg(&b[lane]);
    float qj = __ldg(&q[lane]);
    for (int e = wid; e < N_EDGES; e += NW) {
        const float* eo = (const float*)&g_edge_out[e * 32];
        float acc = 0.0f;
        #pragma unroll 4
        for (int dd = 0; dd < D; dd++) acc += eo[dd] * __ldg(&W[dd * ATT + lane]);
        float t = tanhf(acc + bj) * qj;
        #pragma unroll
        for (int o = 16; o > 0; o >>= 1) t += __shfl_xor_sync(FULL, t, o);
        if (lane == 0) g_logits[e] = t;
    }
}

// ---------------- phase: softmax (block 0 only, NT threads) ----------------
__device__ void softmax_block() {
    __shared__ float red[32];
    int t = threadIdx.x;
    const int nwarp = NT / 32;
    float m = -1e30f;
    for (int e = t; e < N_EDGES; e += NT) m = fmaxf(m, g_logits[e]);
    #pragma unroll
    for (int o = 16; o > 0; o >>= 1) m = fmaxf(m, __shfl_xor_sync(FULL, m, o));
    if ((t & 31) == 0) red[t >> 5] = m;
    __syncthreads();
    if (t < 32) {
        float v = (t < nwarp) ? red[t] : -1e30f;
        #pragma unroll
        for (int o = 16; o > 0; o >>= 1) v = fmaxf(v, __shfl_xor_sync(FULL, v, o));
        if (t == 0) red[0] = v;
    }
    __syncthreads();
    float mx = red[0];
    __syncthreads();
    float s = 0.0f;
    for (int e = t; e < N_EDGES; e += NT) s += expf(g_logits[e] - mx);
    #pragma unroll
    for (int o = 16; o > 0; o >>= 1) s += __shfl_xor_sync(FULL, s, o);
    if ((t & 31) == 0) red[t >> 5] = s;
    __syncthreads();
    if (t < 32) {
        float v = (t < nwarp) ? red[t] : 0.0f;
        #pragma unroll
        for (int o = 16; o > 0; o >>= 1) v += __shfl_xor_sync(FULL, v, o);
        if (t == 0) red[0] = v;
    }
    __syncthreads();
    float inv = 1.0f / red[0];
    for (int e = t; e < N_EDGES; e += NT)
        g_scores[e] = expf(g_logits[e] - mx) * inv;
}

// ---------------- phase: pooled output (warp per dim, deterministic) ----------------
__device__ void pool_phase(int wid, int lane, float* __restrict__ out) {
    if (wid >= D) return;
    int d = wid;
    const float* eo = (const float*)g_edge_out;
    float acc = 0.0f;
    #pragma unroll 4
    for (int e = lane; e < N_EDGES; e += 32)
        acc += g_scores[e] * eo[e * D + d];
    #pragma unroll
    for (int o = 16; o > 0; o >>= 1) acc += __shfl_xor_sync(FULL, acc, o);
    if (lane == 0) out[d] = acc;
}

// ---------------- fused persistent kernel ----------------
__global__ void __launch_bounds__(NT, 5)
fused_kernel(const float4* __restrict__ x0,
             const float4* __restrict__ gamma,
             const float4* __restrict__ beta,
             const float* __restrict__ W,
             const float* __restrict__ b,
             const float* __restrict__ q,
             float* __restrict__ out) {
    int gtid = blockIdx.x * NT + threadIdx.x;
    int wid = gtid >> 5;
    int lane = threadIdx.x & 31;

    // P0: degree inverses
    if (gtid < N_NODES) {
        g_dv_inv[gtid] = 1.0f / fmaxf((float)g_node_cnt[gtid], DEG_EPS);
        if (gtid < N_EDGES)
            g_de_inv[gtid] = 1.0f / fmaxf((float)g_edge_cnt[gtid], DEG_EPS);
    }
    gsync();

    for (int l = 0; l < 4; l++) {
        v2e_phase<false>(wid, lane);
        gsync();
        e2v_phase(wid, lane, x0, gamma, beta);
        gsync();
    }
    v2e_phase<true>(wid, lane);
    gsync();

    logits_phase(wid, lane, W, b, q);
    gsync();

    if (blockIdx.x == 0) softmax_block();
    gsync();

    pool_phase(wid, lane, out);
}

// ---------------- launch ----------------
extern "C" void kernel_launch(void* const* d_in, const int* in_sizes, int n_in,
                              void* d_out, int out_size) {
    const float* x0    = (const float*)d_in[0];
    const float* H     = (const float*)d_in[1];
    const float* gamma = (const float*)d_in[2];
    const float* beta  = (const float*)d_in[3];
    const float* W     = (const float*)d_in[4];
    const float* b     = (const float*)d_in[5];
    const float* q     = (const float*)d_in[6];
    float* out = (float*)d_out;

    init_kernel<<<2048, 256>>>((const float4*)x0);
    build_kernel<<<4096, 256>>>(H);
    fused_kernel<<<NB, NT>>>((const float4*)x0, (const float4*)gamma,
                             (const float4*)beta, W, b, q, out);
}